// round 2
// baseline (speedup 1.0000x reference)
#include <cuda_runtime.h>
#include <math.h>

// ---------------------------------------------------------------------------
// SlotAttention — B=32, F=4096, S=8, D=512, H=2048, 3 iterations.
//
// Restructured so K/V are never materialized:
//   dots    = (s_n @ (w_q @ w_k^T)) @ LNf^T          (per-feature, local)
//   softmax over S=8 is local per feature column
//   updates = ((attn+eps) @ LNf) / rowsum @ w_v
// One fused pass over `features` per iteration computes attention logits,
// softmax, rowsums and the attn^T@LNf contraction.
// ---------------------------------------------------------------------------

#define B_ 32
#define F_ 4096
#define S_ 8
#define D_ 512
#define H_ 2048
#define NITERS_ 3
#define CHUNK 128
#define NCHUNK (F_ / CHUNK) /* 32 */

static __device__ __constant__ float kEPS = 1e-8f;
#define LN_EPS 1e-5f
#define SCALE_ 0.04419417382415922f /* 512^-0.5 */

// -------------------- scratch (device globals; no runtime alloc) ------------
__device__ float g_stats[B_ * F_ * 2];          // per-feature-row mean, rstd
__device__ float g_Wqk[D_ * D_];                // w_q @ w_k^T
__device__ float g_slots[B_ * S_ * D_];
__device__ float g_sn[B_ * S_ * D_];
__device__ float g_qk[B_ * S_ * D_];
__device__ float g_gh[B_ * S_ * 3 * D_];
__device__ float g_gi[B_ * S_ * 3 * D_];
__device__ float g_upv[B_ * S_ * D_];           // updates (pre w_v projection)
__device__ float g_updates[B_ * S_ * D_];
__device__ float g_slots2[B_ * S_ * D_];
__device__ float g_mlpin[B_ * S_ * D_];
__device__ float g_hbuf[B_ * S_ * H_];
__device__ float g_Upart[B_ * NCHUNK * S_ * D_];  // 16 MB partials
__device__ float g_rspart[B_ * NCHUNK * S_];

// -------------------- small utility kernels --------------------------------
__global__ void copy_kernel(const float* __restrict__ src, float* __restrict__ dst, int n) {
    int i = blockIdx.x * 256 + threadIdx.x;
    if (i < n) dst[i] = src[i];
}

// per-row mean / rstd of features: one warp per 512-float row
__global__ void feat_stats_kernel(const float* __restrict__ feat) {
    int row = blockIdx.x * 8 + (threadIdx.x >> 5);
    int lane = threadIdx.x & 31;
    const float4* r4 = (const float4*)(feat + (size_t)row * D_);
    float s = 0.f, ss = 0.f;
#pragma unroll
    for (int i = 0; i < 4; i++) {
        float4 v = r4[lane + 32 * i];
        s += v.x + v.y + v.z + v.w;
        ss += v.x * v.x + v.y * v.y + v.z * v.z + v.w * v.w;
    }
#pragma unroll
    for (int o = 16; o; o >>= 1) {
        s += __shfl_xor_sync(0xffffffffu, s, o);
        ss += __shfl_xor_sync(0xffffffffu, ss, o);
    }
    if (lane == 0) {
        float m = s * (1.f / D_);
        float var = ss * (1.f / D_) - m * m;
        g_stats[row * 2] = m;
        g_stats[row * 2 + 1] = rsqrtf(fmaxf(var, 0.f) + LN_EPS);
    }
}

// LayerNorm of [R, 512] rows -> Y (128 threads per row)
__global__ void ln_rows_kernel(const float* __restrict__ X, float* __restrict__ Y,
                               const float* __restrict__ w, const float* __restrict__ b) {
    __shared__ float red[48];
    int row = blockIdx.x;
    const float* x = X + (size_t)row * D_;
    int t = threadIdx.x;
    float v[4];
    float s = 0.f, ss = 0.f;
#pragma unroll
    for (int i = 0; i < 4; i++) {
        v[i] = x[t + 128 * i];
        s += v[i];
        ss += v[i] * v[i];
    }
#pragma unroll
    for (int o = 16; o; o >>= 1) {
        s += __shfl_xor_sync(0xffffffffu, s, o);
        ss += __shfl_xor_sync(0xffffffffu, ss, o);
    }
    int warp = t >> 5, lane = t & 31;
    if (lane == 0) { red[warp] = s; red[warp + 8] = ss; }
    __syncthreads();
    if (t == 0) {
        float S2 = 0.f, SS = 0.f;
        for (int wi = 0; wi < 4; wi++) { S2 += red[wi]; SS += red[wi + 8]; }
        float m = S2 * (1.f / D_);
        red[16] = m;
        red[17] = rsqrtf(fmaxf(SS * (1.f / D_) - m * m, 0.f) + LN_EPS);
    }
    __syncthreads();
    float m = red[16], r = red[17];
    float* y = Y + (size_t)row * D_;
#pragma unroll
    for (int i = 0; i < 4; i++) {
        int d = t + 128 * i;
        y[d] = (v[i] - m) * r * w[d] + b[d];
    }
}

// -------------------- generic tiled SGEMM ----------------------------------
// C[M,N] = A[M,K] @ op(B) (+bias) (+relu) (+residual)
// TRANS_B: B stored [N,K] (compute A @ B^T). M,N %64==0, K %16==0 assumed.
template <bool TRANS_B, bool RELU>
__global__ void gemm_kernel(const float* __restrict__ A, const float* __restrict__ Bm,
                            float* __restrict__ C, int M, int N, int K,
                            const float* __restrict__ bias,
                            const float* __restrict__ residual) {
    const int BM = 64, BN = 64, BK = 16;
    __shared__ float As[BK][BM + 4];
    __shared__ float Bs[BK][BN + 4];
    int bm = blockIdx.y * BM;
    int bn = blockIdx.x * BN;
    int tid = threadIdx.x;
    int tx = tid & 15, ty = tid >> 4;
    float acc[4][4] = {};
    for (int k0 = 0; k0 < K; k0 += BK) {
#pragma unroll
        for (int it = 0; it < 4; it++) {
            int flat = tid + 256 * it;
            int m = flat >> 4;
            int k = flat & 15;
            As[k][m] = A[(size_t)(bm + m) * K + k0 + k];
        }
#pragma unroll
        for (int it = 0; it < 4; it++) {
            int flat = tid + 256 * it;
            if (TRANS_B) {
                int n = flat >> 4;
                int k = flat & 15;
                Bs[k][n] = Bm[(size_t)(bn + n) * K + k0 + k];
            } else {
                int k = flat >> 6;
                int n = flat & 63;
                Bs[k][n] = Bm[(size_t)(k0 + k) * N + bn + n];
            }
        }
        __syncthreads();
#pragma unroll
        for (int k = 0; k < BK; k++) {
            float a[4], bb[4];
#pragma unroll
            for (int i = 0; i < 4; i++) a[i] = As[k][ty * 4 + i];
#pragma unroll
            for (int j = 0; j < 4; j++) bb[j] = Bs[k][tx * 4 + j];
#pragma unroll
            for (int i = 0; i < 4; i++)
#pragma unroll
                for (int j = 0; j < 4; j++) acc[i][j] += a[i] * bb[j];
        }
        __syncthreads();
    }
#pragma unroll
    for (int i = 0; i < 4; i++) {
        int m = bm + ty * 4 + i;
#pragma unroll
        for (int j = 0; j < 4; j++) {
            int n = bn + tx * 4 + j;
            float cv = acc[i][j];
            if (bias) cv += bias[n];
            if (RELU) cv = fmaxf(cv, 0.f);
            if (residual) cv += residual[(size_t)m * N + n];
            C[(size_t)m * N + n] = cv;
        }
    }
}

// -------------------- fused per-iteration feature pass ----------------------
// grid (NCHUNK, B), 256 threads. Phase 1: dots + softmax(S=8) per feature,
// Phase 2: U'[s,d] += (attn+eps)*LN(feat)[f,d] over the chunk (partials).
__global__ void iter_pass_kernel(const float* __restrict__ feat,
                                 const float* __restrict__ lnw,
                                 const float* __restrict__ lnb,
                                 float* __restrict__ attn_out /* null unless last iter */) {
    __shared__ float qk_s[S_ * D_];
    __shared__ float attn_s[CHUNK * S_];
    __shared__ float lnw_s[D_], lnb_s[D_];
    __shared__ float stats_s[CHUNK * 2];
    __shared__ float wsum_s[8][8];

    int chunk = blockIdx.x, b = blockIdx.y;
    int tid = threadIdx.x, warp = tid >> 5, lane = tid & 31;
    int f0 = chunk * CHUNK;

    for (int i = tid; i < S_ * D_; i += 256) qk_s[i] = g_qk[b * S_ * D_ + i];
    for (int i = tid; i < D_; i += 256) { lnw_s[i] = lnw[i]; lnb_s[i] = lnb[i]; }
    for (int i = tid; i < CHUNK * 2; i += 256) stats_s[i] = g_stats[((size_t)b * F_ + f0) * 2 + i];
    __syncthreads();

    // ---- phase 1: one warp per feature row, 16 rows per warp ----
    float wsum[8] = {};
    for (int fl = warp; fl < CHUNK; fl += 8) {
        const float4* r4 = (const float4*)(feat + ((size_t)(b * F_ + f0 + fl)) * D_);
        float mean = stats_s[fl * 2], rstd = stats_s[fl * 2 + 1];
        float acc[8] = {};
#pragma unroll
        for (int i = 0; i < 4; i++) {
            int idx = lane + 32 * i;
            float4 v = r4[idx];
            int dbase = idx * 4;
            float x0 = (v.x - mean) * rstd * lnw_s[dbase]     + lnb_s[dbase];
            float x1 = (v.y - mean) * rstd * lnw_s[dbase + 1] + lnb_s[dbase + 1];
            float x2 = (v.z - mean) * rstd * lnw_s[dbase + 2] + lnb_s[dbase + 2];
            float x3 = (v.w - mean) * rstd * lnw_s[dbase + 3] + lnb_s[dbase + 3];
#pragma unroll
            for (int s = 0; s < 8; s++) {
                const float4 q = *(const float4*)&qk_s[s * D_ + dbase];
                acc[s] += x0 * q.x + x1 * q.y + x2 * q.z + x3 * q.w;
            }
        }
#pragma unroll
        for (int s = 0; s < 8; s++)
#pragma unroll
            for (int o = 16; o; o >>= 1) acc[s] += __shfl_xor_sync(0xffffffffu, acc[s], o);
        // softmax over the 8 slots (identical on every lane)
        float mx = acc[0] * SCALE_;
#pragma unroll
        for (int s = 1; s < 8; s++) mx = fmaxf(mx, acc[s] * SCALE_);
        float e[8], den = 0.f;
#pragma unroll
        for (int s = 0; s < 8; s++) { e[s] = expf(acc[s] * SCALE_ - mx); den += e[s]; }
        float inv = 1.f / den;
        if (lane == 0) {
#pragma unroll
            for (int s = 0; s < 8; s++) {
                float p = e[s] * inv;
                attn_s[fl * 8 + s] = p;
                wsum[s] += p + kEPS;
            }
        }
    }
    if (lane == 0) {
#pragma unroll
        for (int s = 0; s < 8; s++) wsum_s[warp][s] = wsum[s];
    }
    __syncthreads();
    if (tid < 8) {
        float t = 0.f;
#pragma unroll
        for (int w = 0; w < 8; w++) t += wsum_s[w][tid];  // fixed order: deterministic
        g_rspart[(b * NCHUNK + chunk) * 8 + tid] = t;
    }
    if (attn_out) {
        for (int idx = tid; idx < CHUNK * S_; idx += 256) {
            int s = idx >> 7;
            int fl = idx & 127;
            attn_out[((size_t)(b * S_ + s)) * F_ + f0 + fl] = attn_s[fl * 8 + s];
        }
    }

    // ---- phase 2: U'[s,d] partial accumulation; thread -> columns d, d+256 --
    float a0[8] = {}, a1[8] = {};
    const float w0 = lnw_s[tid], c0 = lnb_s[tid];
    const float w1 = lnw_s[tid + 256], c1 = lnb_s[tid + 256];
    for (int fl = 0; fl < CHUNK; fl++) {
        const float* row = feat + ((size_t)(b * F_ + f0 + fl)) * D_;
        float mean = stats_s[fl * 2], rstd = stats_s[fl * 2 + 1];
        float v0 = (row[tid] - mean) * rstd * w0 + c0;
        float v1 = (row[tid + 256] - mean) * rstd * w1 + c1;
#pragma unroll
        for (int s = 0; s < 8; s++) {
            float a = attn_s[fl * 8 + s] + kEPS;
            a0[s] += a * v0;
            a1[s] += a * v1;
        }
    }
    size_t base = ((size_t)(b * NCHUNK + chunk)) * S_ * D_;
#pragma unroll
    for (int s = 0; s < 8; s++) {
        g_Upart[base + s * D_ + tid] = a0[s];
        g_Upart[base + s * D_ + tid + 256] = a1[s];
    }
}

// deterministic reduction of partials + rowsum normalization
__global__ void reduce_updates_kernel() {
    int bs = blockIdx.x;           // b*8+s
    int b = bs >> 3, s = bs & 7;
    int d = threadIdx.x;           // 512 threads
    float rs = 0.f;
#pragma unroll
    for (int c = 0; c < NCHUNK; c++) rs += g_rspart[(b * NCHUNK + c) * 8 + s];
    float acc = 0.f;
    for (int c = 0; c < NCHUNK; c++)
        acc += g_Upart[(((size_t)(b * NCHUNK + c)) * S_ + s) * D_ + d];
    g_updates[(size_t)bs * D_ + d] = acc / rs;
}

// GRU gate combine (torch GRUCell semantics, gates [r,z,n])
__global__ void gru_gate_kernel() {
    int idx = blockIdx.x * 256 + threadIdx.x;  // < 131072
    int r = idx >> 9, d = idx & 511;
    size_t gb = (size_t)r * 3 * D_;
    float ir = g_gi[gb + d],          hr = g_gh[gb + d];
    float iz = g_gi[gb + D_ + d],     hz = g_gh[gb + D_ + d];
    float in_ = g_gi[gb + 2 * D_ + d], hn = g_gh[gb + 2 * D_ + d];
    float rg = 1.f / (1.f + expf(-(ir + hr)));
    float z  = 1.f / (1.f + expf(-(iz + hz)));
    float n  = tanhf(in_ + rg * hn);
    g_slots2[idx] = (1.f - z) * n + z * g_sn[idx];
}

// -------------------- host orchestration -----------------------------------
extern "C" void kernel_launch(void* const* d_in, const int* in_sizes, int n_in,
                              void* d_out, int out_size) {
    const float* slots_in = (const float*)d_in[0];
    const float* features = (const float*)d_in[1];
    const float* w_k      = (const float*)d_in[2];
    const float* w_v      = (const float*)d_in[3];
    const float* w_q      = (const float*)d_in[4];
    const float* ln_feat_w = (const float*)d_in[5];
    const float* ln_feat_b = (const float*)d_in[6];
    const float* ln_slot_w = (const float*)d_in[7];
    const float* ln_slot_b = (const float*)d_in[8];
    const float* gru_w_ih = (const float*)d_in[9];
    const float* gru_w_hh = (const float*)d_in[10];
    const float* gru_b_ih = (const float*)d_in[11];
    const float* gru_b_hh = (const float*)d_in[12];
    const float* ln_mlp_w = (const float*)d_in[13];
    const float* ln_mlp_b = (const float*)d_in[14];
    const float* mlp_w1   = (const float*)d_in[15];
    const float* mlp_b1   = (const float*)d_in[16];
    const float* mlp_w2   = (const float*)d_in[17];
    const float* mlp_b2   = (const float*)d_in[18];

    float* out = (float*)d_out;
    float* out_slots = out;                      // [32,8,512]
    float* out_attn  = out + B_ * S_ * D_;       // [32,8,4096]

    // device-global addresses
    float *p_Wqk, *p_slots, *p_sn, *p_qk, *p_gh, *p_gi, *p_upv, *p_updates,
          *p_slots2, *p_mlpin, *p_hbuf;
    cudaGetSymbolAddress((void**)&p_Wqk, g_Wqk);
    cudaGetSymbolAddress((void**)&p_slots, g_slots);
    cudaGetSymbolAddress((void**)&p_sn, g_sn);
    cudaGetSymbolAddress((void**)&p_qk, g_qk);
    cudaGetSymbolAddress((void**)&p_gh, g_gh);
    cudaGetSymbolAddress((void**)&p_gi, g_gi);
    cudaGetSymbolAddress((void**)&p_upv, g_upv);
    cudaGetSymbolAddress((void**)&p_updates, g_updates);
    cudaGetSymbolAddress((void**)&p_slots2, g_slots2);
    cudaGetSymbolAddress((void**)&p_mlpin, g_mlpin);
    cudaGetSymbolAddress((void**)&p_hbuf, g_hbuf);

    const int NS = B_ * S_;          // 256 slot rows
    const int NSD = NS * D_;         // 131072

    // slots working copy
    copy_kernel<<<(NSD + 255) / 256, 256>>>(slots_in, p_slots, NSD);

    // per-feature-row LN stats (one pass over 256 MB)
    feat_stats_kernel<<<(B_ * F_) / 8, 256>>>(features);

    // Wqk = w_q @ w_k^T  (NT)
    gemm_kernel<true, false><<<dim3(8, 8), 256>>>(w_q, w_k, p_Wqk, D_, D_, D_, nullptr, nullptr);

    for (int it = 0; it < NITERS_; it++) {
        bool last = (it == NITERS_ - 1);

        // s_n = LN(slots)
        ln_rows_kernel<<<NS, 128>>>(p_slots, p_sn, ln_slot_w, ln_slot_b);
        // qk = s_n @ Wqk  (NN)
        gemm_kernel<false, false><<<dim3(8, 4), 256>>>(p_sn, p_Wqk, p_qk, NS, D_, D_, nullptr, nullptr);
        // gh = s_n @ w_hh^T + b_hh  (NT) — independent of the feature pass
        gemm_kernel<true, false><<<dim3(24, 4), 256>>>(p_sn, gru_w_hh, p_gh, NS, 3 * D_, D_, gru_b_hh, nullptr);

        // fused attention pass over features
        iter_pass_kernel<<<dim3(NCHUNK, B_), 256>>>(features, ln_feat_w, ln_feat_b,
                                                    last ? out_attn : nullptr);
        // reduce partials -> normalized updates
        reduce_updates_kernel<<<NS, D_>>>();

        // upv = updates @ w_v  (NN)
        gemm_kernel<false, false><<<dim3(8, 4), 256>>>(p_updates, w_v, p_upv, NS, D_, D_, nullptr, nullptr);
        // gi = upv @ w_ih^T + b_ih  (NT)
        gemm_kernel<true, false><<<dim3(24, 4), 256>>>(p_upv, gru_w_ih, p_gi, NS, 3 * D_, D_, gru_b_ih, nullptr);
        // GRU combine -> slots2
        gru_gate_kernel<<<NSD / 256, 256>>>();

        // residual MLP: slots = slots2 + W2 @ relu(W1 @ LN(slots2) + b1) + b2
        ln_rows_kernel<<<NS, 128>>>(p_slots2, p_mlpin, ln_mlp_w, ln_mlp_b);
        gemm_kernel<false, true><<<dim3(32, 4), 256>>>(p_mlpin, mlp_w1, p_hbuf, NS, H_, D_, mlp_b1, nullptr);
        gemm_kernel<false, false><<<dim3(8, 4), 256>>>(p_hbuf, mlp_w2,
                                                       last ? out_slots : p_slots,
                                                       NS, D_, H_, mlp_b2, p_slots2);
    }
}

// round 3
// speedup vs baseline: 1.4965x; 1.4965x over previous
#include <cuda_runtime.h>
#include <math.h>

// ---------------------------------------------------------------------------
// SlotAttention — B=32, F=4096, S=8, D=512, H=2048, 3 iterations.
// K/V never materialized:
//   dots    = (s_n @ (w_q @ w_k^T)) @ LNf^T
//   softmax over S=8 local per feature
//   updates = ((attn+eps) @ LNf) / rowsum
//   gi      = updates @ (w_v @ w_ih^T)       (w_v GEMM folded away)
//   [qk|gh] = s_n @ [Wqk | w_hh^T]           (one fused GEMM)
// ---------------------------------------------------------------------------

#define B_ 32
#define F_ 4096
#define S_ 8
#define D_ 512
#define H_ 2048
#define NITERS_ 3
#define CHUNK 128
#define NCHUNK (F_ / CHUNK) /* 32 */

static __device__ __constant__ float kEPS = 1e-8f;
#define LN_EPS 1e-5f
#define SCALE_ 0.04419417382415922f /* 512^-0.5 */

// -------------------- scratch (device globals) ------------------------------
__device__ float g_stats[B_ * F_ * 2];
__device__ float g_Wqkhh[D_ * 2048];              // [Wqk | w_hh^T] (512 x 2048)
__device__ float g_bias2048[2048];                // [0 | b_hh]
__device__ float g_Wvih[D_ * 3 * D_];             // w_v @ w_ih^T (512 x 1536)
__device__ float g_slots[B_ * S_ * D_];
__device__ float g_sn[B_ * S_ * D_];
__device__ float g_qkgh[B_ * S_ * 2048];          // cols 0-511 qk, 512-2047 gh
__device__ float g_gi[B_ * S_ * 3 * D_];
__device__ float g_updates[B_ * S_ * D_];
__device__ float g_slots2[B_ * S_ * D_];
__device__ float g_mlpin[B_ * S_ * D_];
__device__ float g_hbuf[B_ * S_ * H_];
__device__ float g_split[4 * B_ * S_ * D_];       // split-K partials
__device__ float g_Upart[B_ * NCHUNK * S_ * D_];  // 16 MB partials
__device__ float g_rspart[B_ * NCHUNK * S_];

// -------------------- small utility kernels --------------------------------
// per-row mean / rstd of features: one warp per 512-float row
__global__ void feat_stats_kernel(const float* __restrict__ feat) {
    int row = blockIdx.x * 8 + (threadIdx.x >> 5);
    int lane = threadIdx.x & 31;
    const float4* r4 = (const float4*)(feat + (size_t)row * D_);
    float s = 0.f, ss = 0.f;
#pragma unroll
    for (int i = 0; i < 4; i++) {
        float4 v = r4[lane + 32 * i];
        s += v.x + v.y + v.z + v.w;
        ss += v.x * v.x + v.y * v.y + v.z * v.z + v.w * v.w;
    }
#pragma unroll
    for (int o = 16; o; o >>= 1) {
        s += __shfl_xor_sync(0xffffffffu, s, o);
        ss += __shfl_xor_sync(0xffffffffu, ss, o);
    }
    if (lane == 0) {
        float m = s * (1.f / D_);
        float var = ss * (1.f / D_) - m * m;
        g_stats[row * 2] = m;
        g_stats[row * 2 + 1] = rsqrtf(fmaxf(var, 0.f) + LN_EPS);
    }
}

// LayerNorm of [R, 512] rows -> Y (128 threads per row)
__global__ void ln_rows_kernel(const float* __restrict__ X, float* __restrict__ Y,
                               const float* __restrict__ w, const float* __restrict__ b) {
    __shared__ float red[48];
    int row = blockIdx.x;
    const float* x = X + (size_t)row * D_;
    int t = threadIdx.x;
    float v[4];
    float s = 0.f, ss = 0.f;
#pragma unroll
    for (int i = 0; i < 4; i++) {
        v[i] = x[t + 128 * i];
        s += v[i];
        ss += v[i] * v[i];
    }
#pragma unroll
    for (int o = 16; o; o >>= 1) {
        s += __shfl_xor_sync(0xffffffffu, s, o);
        ss += __shfl_xor_sync(0xffffffffu, ss, o);
    }
    int warp = t >> 5, lane = t & 31;
    if (lane == 0) { red[warp] = s; red[warp + 8] = ss; }
    __syncthreads();
    if (t == 0) {
        float S2 = 0.f, SS = 0.f;
        for (int wi = 0; wi < 4; wi++) { S2 += red[wi]; SS += red[wi + 8]; }
        float m = S2 * (1.f / D_);
        red[16] = m;
        red[17] = rsqrtf(fmaxf(SS * (1.f / D_) - m * m, 0.f) + LN_EPS);
    }
    __syncthreads();
    float m = red[16], r = red[17];
    float* y = Y + (size_t)row * D_;
#pragma unroll
    for (int i = 0; i < 4; i++) {
        int d = t + 128 * i;
        y[d] = (v[i] - m) * r * w[d] + b[d];
    }
}

// build Wqkhh cols 512..2047 = w_hh^T and the packed bias vector
__global__ void build_whh_kernel(const float* __restrict__ w_hh,
                                 const float* __restrict__ b_hh) {
    int idx = blockIdx.x * 256 + threadIdx.x;
    if (idx < 512 * 1536) {
        int d = idx / 1536, g = idx % 1536;
        g_Wqkhh[(size_t)d * 2048 + 512 + g] = w_hh[(size_t)g * 512 + d];
    }
    if (idx < 2048) g_bias2048[idx] = (idx < 512) ? 0.f : b_hh[idx - 512];
}

// -------------------- SGEMM: 64x64x16 tiles, 128 threads, 8x4 micro ---------
// C[M,N] = A[M,K] @ op(B) (+bias)(+relu)(+residual); gridDim.z = split-K.
// M,N %64==0, K%(16*gridDim.z)==0.
template <bool TRANS_B, bool RELU>
__global__ void gemm64_kernel(const float* __restrict__ A, const float* __restrict__ Bm,
                              float* __restrict__ C, int M, int N, int K, int ldc,
                              const float* __restrict__ bias,
                              const float* __restrict__ residual) {
    __shared__ __align__(16) float As[16][64];
    __shared__ __align__(16) float Bs[16][64];
    const int tid = threadIdx.x;          // 128 threads
    const int bm = blockIdx.y * 64;
    const int bn = blockIdx.x * 64;
    const int Kz = K / gridDim.z;
    const int kbase = blockIdx.z * Kz;
    C += (size_t)blockIdx.z * M * ldc;    // split-K partial slice

    const int tx = tid & 15, ty = tid >> 4;
    float4 pa[2], pb[2];

    const int a_m0 = (tid) >> 2, a_k0 = (tid & 3) * 4;
    const int a_m1 = (tid + 128) >> 2, a_k1 = ((tid + 128) & 3) * 4;
    const int b_kk0 = tid >> 4, b_n0 = (tid & 15) * 4;
    const int b_kk1 = (tid + 128) >> 4, b_n1 = ((tid + 128) & 15) * 4;

    float acc[8][4] = {};
    const int nsteps = Kz / 16;

    // prefetch tile 0
    pa[0] = *(const float4*)(A + (size_t)(bm + a_m0) * K + kbase + a_k0);
    pa[1] = *(const float4*)(A + (size_t)(bm + a_m1) * K + kbase + a_k1);
    if (TRANS_B) {
        pb[0] = *(const float4*)(Bm + (size_t)(bn + a_m0) * K + kbase + a_k0);
        pb[1] = *(const float4*)(Bm + (size_t)(bn + a_m1) * K + kbase + a_k1);
    } else {
        pb[0] = *(const float4*)(Bm + (size_t)(kbase + b_kk0) * N + bn + b_n0);
        pb[1] = *(const float4*)(Bm + (size_t)(kbase + b_kk1) * N + bn + b_n1);
    }

    for (int s = 0; s < nsteps; s++) {
        // stash prefetched tile into smem
        As[a_k0 + 0][a_m0] = pa[0].x; As[a_k0 + 1][a_m0] = pa[0].y;
        As[a_k0 + 2][a_m0] = pa[0].z; As[a_k0 + 3][a_m0] = pa[0].w;
        As[a_k1 + 0][a_m1] = pa[1].x; As[a_k1 + 1][a_m1] = pa[1].y;
        As[a_k1 + 2][a_m1] = pa[1].z; As[a_k1 + 3][a_m1] = pa[1].w;
        if (TRANS_B) {
            Bs[a_k0 + 0][a_m0] = pb[0].x; Bs[a_k0 + 1][a_m0] = pb[0].y;
            Bs[a_k0 + 2][a_m0] = pb[0].z; Bs[a_k0 + 3][a_m0] = pb[0].w;
            Bs[a_k1 + 0][a_m1] = pb[1].x; Bs[a_k1 + 1][a_m1] = pb[1].y;
            Bs[a_k1 + 2][a_m1] = pb[1].z; Bs[a_k1 + 3][a_m1] = pb[1].w;
        } else {
            *(float4*)&Bs[b_kk0][b_n0] = pb[0];
            *(float4*)&Bs[b_kk1][b_n1] = pb[1];
        }
        __syncthreads();
        if (s + 1 < nsteps) {
            int kb = kbase + (s + 1) * 16;
            pa[0] = *(const float4*)(A + (size_t)(bm + a_m0) * K + kb + a_k0);
            pa[1] = *(const float4*)(A + (size_t)(bm + a_m1) * K + kb + a_k1);
            if (TRANS_B) {
                pb[0] = *(const float4*)(Bm + (size_t)(bn + a_m0) * K + kb + a_k0);
                pb[1] = *(const float4*)(Bm + (size_t)(bn + a_m1) * K + kb + a_k1);
            } else {
                pb[0] = *(const float4*)(Bm + (size_t)(kb + b_kk0) * N + bn + b_n0);
                pb[1] = *(const float4*)(Bm + (size_t)(kb + b_kk1) * N + bn + b_n1);
            }
        }
#pragma unroll
        for (int k = 0; k < 16; k++) {
            float4 a0 = *(const float4*)&As[k][ty * 8];
            float4 a1 = *(const float4*)&As[k][ty * 8 + 4];
            float4 b0 = *(const float4*)&Bs[k][tx * 4];
            float av[8] = {a0.x, a0.y, a0.z, a0.w, a1.x, a1.y, a1.z, a1.w};
            float bv[4] = {b0.x, b0.y, b0.z, b0.w};
#pragma unroll
            for (int i = 0; i < 8; i++)
#pragma unroll
                for (int j = 0; j < 4; j++) acc[i][j] += av[i] * bv[j];
        }
        __syncthreads();
    }
#pragma unroll
    for (int i = 0; i < 8; i++) {
        int row = bm + ty * 8 + i;
        int col = bn + tx * 4;
        float4 o = make_float4(acc[i][0], acc[i][1], acc[i][2], acc[i][3]);
        if (bias) {
            o.x += bias[col]; o.y += bias[col + 1]; o.z += bias[col + 2]; o.w += bias[col + 3];
        }
        if (RELU) {
            o.x = fmaxf(o.x, 0.f); o.y = fmaxf(o.y, 0.f);
            o.z = fmaxf(o.z, 0.f); o.w = fmaxf(o.w, 0.f);
        }
        if (residual) {
            const float4 r = *(const float4*)(residual + (size_t)row * ldc + col);
            o.x += r.x; o.y += r.y; o.z += r.z; o.w += r.w;
        }
        *(float4*)(C + (size_t)row * ldc + col) = o;
    }
}

// deterministic split-K reduce (+bias +residual) for mlp2
__global__ void splitk_reduce_kernel(const float* __restrict__ bias,
                                     const float* __restrict__ residual,
                                     float* __restrict__ out) {
    int i = blockIdx.x * 256 + threadIdx.x;   // < 131072
    int col = i & 511;
    float v = bias[col] + residual[i];
#pragma unroll
    for (int z = 0; z < 4; z++) v += g_split[(size_t)z * (B_ * S_ * D_) + i];
    out[i] = v;
}

// -------------------- fused per-iteration feature pass ----------------------
__global__ void iter_pass_kernel(const float* __restrict__ feat,
                                 const float* __restrict__ lnw,
                                 const float* __restrict__ lnb,
                                 float* __restrict__ attn_out) {
    __shared__ __align__(16) float qk_s[S_ * D_];  // reused as reduce buffer
    __shared__ float attn_s[CHUNK * S_];
    __shared__ __align__(16) float lnw_s[D_], lnb_s[D_];
    __shared__ float stats_s[CHUNK * 2];
    __shared__ float wsum_s[8][8];

    int chunk = blockIdx.x, b = blockIdx.y;
    int tid = threadIdx.x, warp = tid >> 5, lane = tid & 31;
    int f0 = chunk * CHUNK;

    for (int i = tid; i < S_ * D_; i += 256) {
        int s = i >> 9, d = i & 511;
        qk_s[i] = g_qkgh[((size_t)(b * 8 + s)) * 2048 + d];
    }
    for (int i = tid; i < D_; i += 256) { lnw_s[i] = lnw[i]; lnb_s[i] = lnb[i]; }
    for (int i = tid; i < CHUNK * 2; i += 256) stats_s[i] = g_stats[((size_t)b * F_ + f0) * 2 + i];
    __syncthreads();

    // ---- phase 1: one warp per feature row ----
    float wsum[8] = {};
    for (int fl = warp; fl < CHUNK; fl += 8) {
        const float4* r4 = (const float4*)(feat + ((size_t)(b * F_ + f0 + fl)) * D_);
        float mean = stats_s[fl * 2], rstd = stats_s[fl * 2 + 1];
        float acc[8] = {};
#pragma unroll
        for (int i = 0; i < 4; i++) {
            int idx = lane + 32 * i;
            float4 v = r4[idx];
            int dbase = idx * 4;
            float x0 = (v.x - mean) * rstd * lnw_s[dbase]     + lnb_s[dbase];
            float x1 = (v.y - mean) * rstd * lnw_s[dbase + 1] + lnb_s[dbase + 1];
            float x2 = (v.z - mean) * rstd * lnw_s[dbase + 2] + lnb_s[dbase + 2];
            float x3 = (v.w - mean) * rstd * lnw_s[dbase + 3] + lnb_s[dbase + 3];
#pragma unroll
            for (int s = 0; s < 8; s++) {
                const float4 q = *(const float4*)&qk_s[s * D_ + dbase];
                acc[s] += x0 * q.x + x1 * q.y + x2 * q.z + x3 * q.w;
            }
        }
#pragma unroll
        for (int s = 0; s < 8; s++)
#pragma unroll
            for (int o = 16; o; o >>= 1) acc[s] += __shfl_xor_sync(0xffffffffu, acc[s], o);
        float mx = acc[0] * SCALE_;
#pragma unroll
        for (int s = 1; s < 8; s++) mx = fmaxf(mx, acc[s] * SCALE_);
        float e[8], den = 0.f;
#pragma unroll
        for (int s = 0; s < 8; s++) { e[s] = expf(acc[s] * SCALE_ - mx); den += e[s]; }
        float inv = 1.f / den;
        if (lane == 0) {
#pragma unroll
            for (int s = 0; s < 8; s++) {
                float p = e[s] * inv;
                attn_s[fl * 8 + s] = p;
                wsum[s] += p + kEPS;
            }
        }
    }
    if (lane == 0) {
#pragma unroll
        for (int s = 0; s < 8; s++) wsum_s[warp][s] = wsum[s];
    }
    __syncthreads();
    if (tid < 8) {
        float t = 0.f;
#pragma unroll
        for (int w = 0; w < 8; w++) t += wsum_s[w][tid];
        g_rspart[(b * NCHUNK + chunk) * 8 + tid] = t;
    }
    if (attn_out) {
        for (int idx = tid; idx < CHUNK * S_; idx += 256) {
            int s = idx >> 7;
            int fl = idx & 127;
            attn_out[((size_t)(b * S_ + s)) * F_ + f0 + fl] = attn_s[fl * 8 + s];
        }
    }

    // ---- phase 2: vectorized; halves of the chunk per thread group ----
    int half = tid >> 7;              // 0: rows 0-63, 1: rows 64-127
    int d4 = (tid & 127) * 4;
    float4 w4 = *(const float4*)&lnw_s[d4];
    float4 c4 = *(const float4*)&lnb_s[d4];
    float4 acc[8];
#pragma unroll
    for (int s = 0; s < 8; s++) acc[s] = make_float4(0.f, 0.f, 0.f, 0.f);

    int fl0 = half * 64;
    for (int fl = fl0; fl < fl0 + 64; fl++) {
        const float4 v = *(const float4*)(feat + ((size_t)(b * F_ + f0 + fl)) * D_ + d4);
        float mean = stats_s[fl * 2], rstd = stats_s[fl * 2 + 1];
        // x = v * (rstd*w) + (b - mean*rstd*w)
        float4 rw, cc, x;
        rw.x = rstd * w4.x; rw.y = rstd * w4.y; rw.z = rstd * w4.z; rw.w = rstd * w4.w;
        cc.x = c4.x - mean * rw.x; cc.y = c4.y - mean * rw.y;
        cc.z = c4.z - mean * rw.z; cc.w = c4.w - mean * rw.w;
        x.x = v.x * rw.x + cc.x; x.y = v.y * rw.y + cc.y;
        x.z = v.z * rw.z + cc.z; x.w = v.w * rw.w + cc.w;
        float a[8];
#pragma unroll
        for (int s = 0; s < 8; s++) a[s] = attn_s[fl * 8 + s] + kEPS;
#pragma unroll
        for (int s = 0; s < 8; s++) {
            acc[s].x += a[s] * x.x; acc[s].y += a[s] * x.y;
            acc[s].z += a[s] * x.z; acc[s].w += a[s] * x.w;
        }
    }
    __syncthreads();     // attn_s / qk_s reads done; reuse qk_s for reduction
    if (half == 0) {
#pragma unroll
        for (int s = 0; s < 8; s++) *(float4*)&qk_s[s * D_ + d4] = acc[s];
    }
    __syncthreads();
    if (half == 1) {
        size_t base = ((size_t)(b * NCHUNK + chunk)) * S_ * D_;
#pragma unroll
        for (int s = 0; s < 8; s++) {
            float4 o = *(const float4*)&qk_s[s * D_ + d4];
            o.x += acc[s].x; o.y += acc[s].y; o.z += acc[s].z; o.w += acc[s].w;
            *(float4*)(&g_Upart[base + s * D_ + d4]) = o;
        }
    }
}

// deterministic reduction of partials + rowsum normalization
__global__ void reduce_updates_kernel() {
    int bs = blockIdx.x;           // b*8+s
    int b = bs >> 3, s = bs & 7;
    int d = threadIdx.x;           // 512 threads
    float rs = 0.f;
#pragma unroll
    for (int c = 0; c < NCHUNK; c++) rs += g_rspart[(b * NCHUNK + c) * 8 + s];
    float acc = 0.f;
    for (int c = 0; c < NCHUNK; c++)
        acc += g_Upart[(((size_t)(b * NCHUNK + c)) * S_ + s) * D_ + d];
    g_updates[(size_t)bs * D_ + d] = acc / rs;
}

// GRU gate combine (torch GRUCell, gates [r,z,n]); gh lives in g_qkgh[...,512:]
__global__ void gru_gate_kernel() {
    int idx = blockIdx.x * 256 + threadIdx.x;  // < 131072
    int r = idx >> 9, d = idx & 511;
    size_t gib = (size_t)r * 3 * D_;
    size_t ghb = (size_t)r * 2048 + 512;
    float ir = g_gi[gib + d],           hr = g_qkgh[ghb + d];
    float iz = g_gi[gib + D_ + d],      hz = g_qkgh[ghb + D_ + d];
    float in_ = g_gi[gib + 2 * D_ + d], hn = g_qkgh[ghb + 2 * D_ + d];
    float rg = 1.f / (1.f + expf(-(ir + hr)));
    float z  = 1.f / (1.f + expf(-(iz + hz)));
    float n  = tanhf(in_ + rg * hn);
    g_slots2[idx] = (1.f - z) * n + z * g_sn[idx];
}

// -------------------- host orchestration -----------------------------------
extern "C" void kernel_launch(void* const* d_in, const int* in_sizes, int n_in,
                              void* d_out, int out_size) {
    const float* slots_in = (const float*)d_in[0];
    const float* features = (const float*)d_in[1];
    const float* w_k      = (const float*)d_in[2];
    const float* w_v      = (const float*)d_in[3];
    const float* w_q      = (const float*)d_in[4];
    const float* ln_feat_w = (const float*)d_in[5];
    const float* ln_feat_b = (const float*)d_in[6];
    const float* ln_slot_w = (const float*)d_in[7];
    const float* ln_slot_b = (const float*)d_in[8];
    const float* gru_w_ih = (const float*)d_in[9];
    const float* gru_w_hh = (const float*)d_in[10];
    const float* gru_b_ih = (const float*)d_in[11];
    // d_in[12] = gru_b_hh (packed into g_bias2048)
    const float* gru_b_hh = (const float*)d_in[12];
    const float* ln_mlp_w = (const float*)d_in[13];
    const float* ln_mlp_b = (const float*)d_in[14];
    const float* mlp_w1   = (const float*)d_in[15];
    const float* mlp_b1   = (const float*)d_in[16];
    const float* mlp_w2   = (const float*)d_in[17];
    const float* mlp_b2   = (const float*)d_in[18];

    float* out = (float*)d_out;
    float* out_slots = out;                      // [32,8,512]
    float* out_attn  = out + B_ * S_ * D_;       // [32,8,4096]

    float *p_Wqkhh, *p_bias2048, *p_Wvih, *p_slots, *p_sn, *p_qkgh, *p_gi,
          *p_updates, *p_slots2, *p_mlpin, *p_hbuf, *p_split;
    cudaGetSymbolAddress((void**)&p_Wqkhh, g_Wqkhh);
    cudaGetSymbolAddress((void**)&p_bias2048, g_bias2048);
    cudaGetSymbolAddress((void**)&p_Wvih, g_Wvih);
    cudaGetSymbolAddress((void**)&p_slots, g_slots);
    cudaGetSymbolAddress((void**)&p_sn, g_sn);
    cudaGetSymbolAddress((void**)&p_qkgh, g_qkgh);
    cudaGetSymbolAddress((void**)&p_gi, g_gi);
    cudaGetSymbolAddress((void**)&p_updates, g_updates);
    cudaGetSymbolAddress((void**)&p_slots2, g_slots2);
    cudaGetSymbolAddress((void**)&p_mlpin, g_mlpin);
    cudaGetSymbolAddress((void**)&p_hbuf, g_hbuf);
    cudaGetSymbolAddress((void**)&p_split, g_split);

    const int NS = B_ * S_;          // 256 slot rows
    const int NSD = NS * D_;         // 131072

    // -------- precomputes (independent; overlapped only by HW) --------
    feat_stats_kernel<<<(B_ * F_) / 8, 256>>>(features);
    // Wqkhh[:, 0:512] = w_q @ w_k^T  (NT), ldc=2048
    gemm64_kernel<true, false><<<dim3(8, 8, 1), 128>>>(
        w_q, w_k, p_Wqkhh, D_, D_, D_, 2048, nullptr, nullptr);
    // Wqkhh[:, 512:2048] = w_hh^T ; bias2048 = [0 | b_hh]
    build_whh_kernel<<<(512 * 1536 + 255) / 256, 256>>>(gru_w_hh, gru_b_hh);
    // W_vih = w_v @ w_ih^T  (NT) [512 x 1536]
    gemm64_kernel<true, false><<<dim3(24, 8, 1), 128>>>(
        w_v, gru_w_ih, p_Wvih, D_, 3 * D_, D_, 3 * D_, nullptr, nullptr);

    for (int it = 0; it < NITERS_; it++) {
        bool last = (it == NITERS_ - 1);
        const float* slots_src = (it == 0) ? slots_in : p_slots;

        // s_n = LN(slots)
        ln_rows_kernel<<<NS, 128>>>(slots_src, p_sn, ln_slot_w, ln_slot_b);
        // [qk | gh] = s_n @ Wqkhh + [0 | b_hh]   (NN, N=2048)
        gemm64_kernel<false, false><<<dim3(32, 4, 1), 128>>>(
            p_sn, p_Wqkhh, p_qkgh, NS, 2048, D_, 2048, p_bias2048, nullptr);

        // fused attention pass over features
        iter_pass_kernel<<<dim3(NCHUNK, B_), 256>>>(features, ln_feat_w, ln_feat_b,
                                                    last ? out_attn : nullptr);
        reduce_updates_kernel<<<NS, D_>>>();

        // gi = updates @ W_vih + b_ih   (NN, N=1536)
        gemm64_kernel<false, false><<<dim3(24, 4, 1), 128>>>(
            p_updates, p_Wvih, p_gi, NS, 3 * D_, D_, 3 * D_, gru_b_ih, nullptr);
        gru_gate_kernel<<<NSD / 256, 256>>>();

        // residual MLP
        ln_rows_kernel<<<NS, 128>>>(p_slots2, p_mlpin, ln_mlp_w, ln_mlp_b);
        gemm64_kernel<false, true><<<dim3(32, 4, 1), 128>>>(
            p_mlpin, mlp_w1, p_hbuf, NS, H_, D_, H_, mlp_b1, nullptr);
        // mlp2 split-K=4 partials, then deterministic reduce (+b2 +slots2)
        gemm64_kernel<false, false><<<dim3(8, 4, 4), 128>>>(
            p_hbuf, mlp_w2, p_split, NS, D_, H_, D_, nullptr, nullptr);
        splitk_reduce_kernel<<<NSD / 256, 256>>>(mlp_b2, p_slots2,
                                                 last ? out_slots : p_slots);
    }
}

// round 4
// speedup vs baseline: 1.8332x; 1.2250x over previous
#include <cuda_runtime.h>
#include <math.h>

// ---------------------------------------------------------------------------
// SlotAttention — B=32, F=4096, S=8, D=512, H=2048, 3 iterations.
// K/V never materialized; all slot-side GEMMs use split-K partials with
// deterministic fixed-order reduction to raise SM occupancy.
// ---------------------------------------------------------------------------

#define B_ 32
#define F_ 4096
#define S_ 8
#define D_ 512
#define H_ 2048
#define NITERS_ 3
#define CHUNK 128
#define NCHUNK (F_ / CHUNK) /* 32 */

static __device__ __constant__ float kEPS = 1e-8f;
#define LN_EPS 1e-5f
#define SCALE_ 0.04419417382415922f /* 512^-0.5 */

// -------------------- scratch (device globals) ------------------------------
__device__ float g_stats[B_ * F_ * 2];
__device__ float g_Wqkhh[D_ * 2048];              // [Wqk | w_hh^T] (512 x 2048)
__device__ float g_bias2048[2048];                // [0 | b_hh]
__device__ float g_Wvih[D_ * 3 * D_];             // w_v @ w_ih^T (512 x 1536)
__device__ float g_sn[B_ * S_ * D_];
__device__ float g_qkgh[B_ * S_ * 2048];          // cols 0-511 qk, 512-2047 gh
__device__ float g_gi[B_ * S_ * 3 * D_];          // also reused as Wqk tmp
__device__ float g_updates[B_ * S_ * D_];
__device__ float g_slots2[B_ * S_ * D_];
__device__ float g_mlpin[B_ * S_ * D_];
__device__ float g_hbuf[B_ * S_ * H_];
__device__ float g_split[8 * B_ * S_ * 2048];     // split-K partials (16 MB)
__device__ float g_Upart[B_ * NCHUNK * S_ * D_];  // 16 MB partials
__device__ float g_rspart[B_ * NCHUNK * S_];

// -------------------- small utility kernels --------------------------------
__global__ void feat_stats_kernel(const float* __restrict__ feat) {
    int row = blockIdx.x * 8 + (threadIdx.x >> 5);
    int lane = threadIdx.x & 31;
    const float4* r4 = (const float4*)(feat + (size_t)row * D_);
    float s = 0.f, ss = 0.f;
#pragma unroll
    for (int i = 0; i < 4; i++) {
        float4 v = r4[lane + 32 * i];
        s += v.x + v.y + v.z + v.w;
        ss += v.x * v.x + v.y * v.y + v.z * v.z + v.w * v.w;
    }
#pragma unroll
    for (int o = 16; o; o >>= 1) {
        s += __shfl_xor_sync(0xffffffffu, s, o);
        ss += __shfl_xor_sync(0xffffffffu, ss, o);
    }
    if (lane == 0) {
        float m = s * (1.f / D_);
        float var = ss * (1.f / D_) - m * m;
        g_stats[row * 2] = m;
        g_stats[row * 2 + 1] = rsqrtf(fmaxf(var, 0.f) + LN_EPS);
    }
}

// LayerNorm of [R, 512] rows -> Y (128 threads per row) — used only at iter 0
__global__ void ln_rows_kernel(const float* __restrict__ X, float* __restrict__ Y,
                               const float* __restrict__ w, const float* __restrict__ b) {
    __shared__ float red[48];
    int row = blockIdx.x;
    const float* x = X + (size_t)row * D_;
    int t = threadIdx.x;
    float v[4];
    float s = 0.f, ss = 0.f;
#pragma unroll
    for (int i = 0; i < 4; i++) {
        v[i] = x[t + 128 * i];
        s += v[i];
        ss += v[i] * v[i];
    }
#pragma unroll
    for (int o = 16; o; o >>= 1) {
        s += __shfl_xor_sync(0xffffffffu, s, o);
        ss += __shfl_xor_sync(0xffffffffu, ss, o);
    }
    int warp = t >> 5, lane = t & 31;
    if (lane == 0) { red[warp] = s; red[warp + 8] = ss; }
    __syncthreads();
    if (t == 0) {
        float S2 = 0.f, SS = 0.f;
        for (int wi = 0; wi < 4; wi++) { S2 += red[wi]; SS += red[wi + 8]; }
        float m = S2 * (1.f / D_);
        red[16] = m;
        red[17] = rsqrtf(fmaxf(SS * (1.f / D_) - m * m, 0.f) + LN_EPS);
    }
    __syncthreads();
    float m = red[16], r = red[17];
    float* y = Y + (size_t)row * D_;
#pragma unroll
    for (int i = 0; i < 4; i++) {
        int d = t + 128 * i;
        y[d] = (v[i] - m) * r * w[d] + b[d];
    }
}

// pack Wqkhh = [Wqk(from tmp) | w_hh^T]; bias2048 = [0 | b_hh]
__global__ void build_whh_kernel(const float* __restrict__ w_hh,
                                 const float* __restrict__ b_hh,
                                 const float* __restrict__ wqk_tmp) {
    int idx = blockIdx.x * 256 + threadIdx.x;   // < 512*2048
    int d = idx >> 11, col = idx & 2047;
    g_Wqkhh[idx] = (col < 512) ? wqk_tmp[(size_t)d * 512 + col]
                               : w_hh[(size_t)(col - 512) * 512 + d];
    if (idx < 2048) g_bias2048[idx] = (idx < 512) ? 0.f : b_hh[idx - 512];
}

// -------------------- SGEMM: 64x64x16 tiles, 128 threads, 8x4 micro ---------
// gridDim.z = split-K slices; partials written to consecutive [M x ldc] slabs.
template <bool TRANS_B>
__global__ void gemm64_kernel(const float* __restrict__ A, const float* __restrict__ Bm,
                              float* __restrict__ C, int M, int N, int K, int ldc) {
    __shared__ __align__(16) float As[16][64];
    __shared__ __align__(16) float Bs[16][64];
    const int tid = threadIdx.x;          // 128 threads
    const int bm = blockIdx.y * 64;
    const int bn = blockIdx.x * 64;
    const int Kz = K / gridDim.z;
    const int kbase = blockIdx.z * Kz;
    C += (size_t)blockIdx.z * M * ldc;

    const int tx = tid & 15, ty = tid >> 4;
    float4 pa[2], pb[2];

    const int a_m0 = tid >> 2, a_k0 = (tid & 3) * 4;
    const int a_m1 = (tid + 128) >> 2, a_k1 = ((tid + 128) & 3) * 4;
    const int b_kk0 = tid >> 4, b_n0 = (tid & 15) * 4;
    const int b_kk1 = (tid + 128) >> 4, b_n1 = ((tid + 128) & 15) * 4;

    float acc[8][4] = {};
    const int nsteps = Kz / 16;

    pa[0] = *(const float4*)(A + (size_t)(bm + a_m0) * K + kbase + a_k0);
    pa[1] = *(const float4*)(A + (size_t)(bm + a_m1) * K + kbase + a_k1);
    if (TRANS_B) {
        pb[0] = *(const float4*)(Bm + (size_t)(bn + a_m0) * K + kbase + a_k0);
        pb[1] = *(const float4*)(Bm + (size_t)(bn + a_m1) * K + kbase + a_k1);
    } else {
        pb[0] = *(const float4*)(Bm + (size_t)(kbase + b_kk0) * N + bn + b_n0);
        pb[1] = *(const float4*)(Bm + (size_t)(kbase + b_kk1) * N + bn + b_n1);
    }

    for (int s = 0; s < nsteps; s++) {
        As[a_k0 + 0][a_m0] = pa[0].x; As[a_k0 + 1][a_m0] = pa[0].y;
        As[a_k0 + 2][a_m0] = pa[0].z; As[a_k0 + 3][a_m0] = pa[0].w;
        As[a_k1 + 0][a_m1] = pa[1].x; As[a_k1 + 1][a_m1] = pa[1].y;
        As[a_k1 + 2][a_m1] = pa[1].z; As[a_k1 + 3][a_m1] = pa[1].w;
        if (TRANS_B) {
            Bs[a_k0 + 0][a_m0] = pb[0].x; Bs[a_k0 + 1][a_m0] = pb[0].y;
            Bs[a_k0 + 2][a_m0] = pb[0].z; Bs[a_k0 + 3][a_m0] = pb[0].w;
            Bs[a_k1 + 0][a_m1] = pb[1].x; Bs[a_k1 + 1][a_m1] = pb[1].y;
            Bs[a_k1 + 2][a_m1] = pb[1].z; Bs[a_k1 + 3][a_m1] = pb[1].w;
        } else {
            *(float4*)&Bs[b_kk0][b_n0] = pb[0];
            *(float4*)&Bs[b_kk1][b_n1] = pb[1];
        }
        __syncthreads();
        if (s + 1 < nsteps) {
            int kb = kbase + (s + 1) * 16;
            pa[0] = *(const float4*)(A + (size_t)(bm + a_m0) * K + kb + a_k0);
            pa[1] = *(const float4*)(A + (size_t)(bm + a_m1) * K + kb + a_k1);
            if (TRANS_B) {
                pb[0] = *(const float4*)(Bm + (size_t)(bn + a_m0) * K + kb + a_k0);
                pb[1] = *(const float4*)(Bm + (size_t)(bn + a_m1) * K + kb + a_k1);
            } else {
                pb[0] = *(const float4*)(Bm + (size_t)(kb + b_kk0) * N + bn + b_n0);
                pb[1] = *(const float4*)(Bm + (size_t)(kb + b_kk1) * N + bn + b_n1);
            }
        }
#pragma unroll
        for (int k = 0; k < 16; k++) {
            float4 a0 = *(const float4*)&As[k][ty * 8];
            float4 a1 = *(const float4*)&As[k][ty * 8 + 4];
            float4 b0 = *(const float4*)&Bs[k][tx * 4];
            float av[8] = {a0.x, a0.y, a0.z, a0.w, a1.x, a1.y, a1.z, a1.w};
            float bv[4] = {b0.x, b0.y, b0.z, b0.w};
#pragma unroll
            for (int i = 0; i < 8; i++)
#pragma unroll
                for (int j = 0; j < 4; j++) acc[i][j] += av[i] * bv[j];
        }
        __syncthreads();
    }
#pragma unroll
    for (int i = 0; i < 8; i++) {
        int row = bm + ty * 8 + i;
        *(float4*)(C + (size_t)row * ldc + bn + tx * 4) =
            make_float4(acc[i][0], acc[i][1], acc[i][2], acc[i][3]);
    }
}

// deterministic split-K reduce: out[row*ldo+col] = relu?(sum_z + bias[col])
template <bool RELU>
__global__ void splitk_reduce(const float* __restrict__ bias, float* __restrict__ out,
                              int n, int ncols, int ldo, int nsplit, int stride) {
    int i = blockIdx.x * 256 + threadIdx.x;
    if (i >= n) return;
    float v = 0.f;
    for (int z = 0; z < nsplit; z++) v += g_split[(size_t)z * stride + i];
    int row = i / ncols, col = i - row * ncols;
    if (bias) v += bias[col];
    if (RELU) v = fmaxf(v, 0.f);
    out[(size_t)row * ldo + col] = v;
}

// -------------------- fused row kernels (512 threads = 1 row) ---------------
__device__ __forceinline__ void block_ln_512(float v, float* red, int t,
                                             float& m_out, float& r_out) {
    float s = v, ss = v * v;
#pragma unroll
    for (int o = 16; o; o >>= 1) {
        s += __shfl_xor_sync(0xffffffffu, s, o);
        ss += __shfl_xor_sync(0xffffffffu, ss, o);
    }
    int warp = t >> 5, lane = t & 31;
    if (lane == 0) { red[warp] = s; red[warp + 16] = ss; }
    __syncthreads();
    if (t == 0) {
        float S2 = 0.f, SS = 0.f;
#pragma unroll
        for (int wi = 0; wi < 16; wi++) { S2 += red[wi]; SS += red[wi + 16]; }
        float m = S2 * (1.f / D_);
        red[32] = m;
        red[33] = rsqrtf(fmaxf(SS * (1.f / D_) - m * m, 0.f) + LN_EPS);
    }
    __syncthreads();
    m_out = red[32];
    r_out = red[33];
}

// GRU combine + LN(ln_mlp) -> slots2, mlpin.  gh lives in g_qkgh[...,512:]
__global__ void gru_ln_kernel(const float* __restrict__ lnw, const float* __restrict__ lnb) {
    __shared__ float red[34];
    int r = blockIdx.x, d = threadIdx.x;
    size_t gib = (size_t)r * 3 * D_;
    size_t ghb = (size_t)r * 2048 + 512;
    float ir = g_gi[gib + d],           hr = g_qkgh[ghb + d];
    float iz = g_gi[gib + D_ + d],      hz = g_qkgh[ghb + D_ + d];
    float in_ = g_gi[gib + 2 * D_ + d], hn = g_qkgh[ghb + 2 * D_ + d];
    float rg = 1.f / (1.f + expf(-(ir + hr)));
    float z  = 1.f / (1.f + expf(-(iz + hz)));
    float n  = tanhf(in_ + rg * hn);
    float v  = (1.f - z) * n + z * g_sn[(size_t)r * D_ + d];
    g_slots2[(size_t)r * D_ + d] = v;
    float m, rs;
    block_ln_512(v, red, d, m, rs);
    g_mlpin[(size_t)r * D_ + d] = (v - m) * rs * lnw[d] + lnb[d];
}

// mlp2 split-16 reduce + b2 + residual(slots2) + LN(ln_slot) -> sn (+out last)
__global__ void mlp2_reduce_ln(const float* __restrict__ b2,
                               const float* __restrict__ lnw, const float* __restrict__ lnb,
                               float* __restrict__ out_slots /* null unless last */) {
    __shared__ float red[34];
    int r = blockIdx.x, d = threadIdx.x;
    size_t i = (size_t)r * D_ + d;
    float v = b2[d] + g_slots2[i];
#pragma unroll
    for (int z = 0; z < 16; z++) v += g_split[(size_t)z * (B_ * S_ * D_) + i];
    if (out_slots) out_slots[i] = v;
    float m, rs;
    block_ln_512(v, red, d, m, rs);
    g_sn[i] = (v - m) * rs * lnw[d] + lnb[d];
}

// -------------------- fused per-iteration feature pass ----------------------
__global__ void iter_pass_kernel(const float* __restrict__ feat,
                                 const float* __restrict__ lnw,
                                 const float* __restrict__ lnb,
                                 float* __restrict__ attn_out) {
    __shared__ __align__(16) float qk_s[S_ * D_];  // reused as reduce buffer
    __shared__ __align__(16) float attn_s[CHUNK * S_];
    __shared__ __align__(16) float lnw_s[D_], lnb_s[D_];
    __shared__ float stats_s[CHUNK * 2];
    __shared__ float wsum_s[8][8];

    int chunk = blockIdx.x, b = blockIdx.y;
    int tid = threadIdx.x, warp = tid >> 5, lane = tid & 31;
    int f0 = chunk * CHUNK;

    for (int i = tid; i < S_ * D_; i += 256) {
        int s = i >> 9, d = i & 511;
        qk_s[i] = g_qkgh[((size_t)(b * 8 + s)) * 2048 + d];
    }
    for (int i = tid; i < D_; i += 256) { lnw_s[i] = lnw[i]; lnb_s[i] = lnb[i]; }
    for (int i = tid; i < CHUNK * 2; i += 256) stats_s[i] = g_stats[((size_t)b * F_ + f0) * 2 + i];
    __syncthreads();

    // ---- phase 1: one warp per feature row ----
    float wsum[8] = {};
    for (int fl = warp; fl < CHUNK; fl += 8) {
        const float4* r4 = (const float4*)(feat + ((size_t)(b * F_ + f0 + fl)) * D_);
        float mean = stats_s[fl * 2], rstd = stats_s[fl * 2 + 1];
        float acc[8] = {};
#pragma unroll
        for (int i = 0; i < 4; i++) {
            int idx = lane + 32 * i;
            float4 v = r4[idx];
            int dbase = idx * 4;
            float x0 = (v.x - mean) * rstd * lnw_s[dbase]     + lnb_s[dbase];
            float x1 = (v.y - mean) * rstd * lnw_s[dbase + 1] + lnb_s[dbase + 1];
            float x2 = (v.z - mean) * rstd * lnw_s[dbase + 2] + lnb_s[dbase + 2];
            float x3 = (v.w - mean) * rstd * lnw_s[dbase + 3] + lnb_s[dbase + 3];
#pragma unroll
            for (int s = 0; s < 8; s++) {
                const float4 q = *(const float4*)&qk_s[s * D_ + dbase];
                acc[s] += x0 * q.x + x1 * q.y + x2 * q.z + x3 * q.w;
            }
        }
#pragma unroll
        for (int s = 0; s < 8; s++)
#pragma unroll
            for (int o = 16; o; o >>= 1) acc[s] += __shfl_xor_sync(0xffffffffu, acc[s], o);
        float mx = acc[0] * SCALE_;
#pragma unroll
        for (int s = 1; s < 8; s++) mx = fmaxf(mx, acc[s] * SCALE_);
        float e[8], den = 0.f;
#pragma unroll
        for (int s = 0; s < 8; s++) { e[s] = expf(acc[s] * SCALE_ - mx); den += e[s]; }
        float inv = 1.f / den;
        if (lane == 0) {
#pragma unroll
            for (int s = 0; s < 8; s++) {
                float p = e[s] * inv;
                attn_s[fl * 8 + s] = p;
                wsum[s] += p + kEPS;
            }
        }
    }
    if (lane == 0) {
#pragma unroll
        for (int s = 0; s < 8; s++) wsum_s[warp][s] = wsum[s];
    }
    __syncthreads();
    if (tid < 8) {
        float t = 0.f;
#pragma unroll
        for (int w = 0; w < 8; w++) t += wsum_s[w][tid];
        g_rspart[(b * NCHUNK + chunk) * 8 + tid] = t;
    }
    if (attn_out) {
        for (int idx = tid; idx < CHUNK * S_; idx += 256) {
            int s = idx >> 7;
            int fl = idx & 127;
            attn_out[((size_t)(b * S_ + s)) * F_ + f0 + fl] = attn_s[fl * 8 + s];
        }
    }

    // ---- phase 2: vectorized; halves of the chunk per thread group ----
    int half = tid >> 7;              // 0: rows 0-63, 1: rows 64-127
    int d4 = (tid & 127) * 4;
    float4 w4 = *(const float4*)&lnw_s[d4];
    float4 c4 = *(const float4*)&lnb_s[d4];
    float4 acc[8];
#pragma unroll
    for (int s = 0; s < 8; s++) acc[s] = make_float4(0.f, 0.f, 0.f, 0.f);

    int fl0 = half * 64;
    for (int fl = fl0; fl < fl0 + 64; fl++) {
        const float4 v = *(const float4*)(feat + ((size_t)(b * F_ + f0 + fl)) * D_ + d4);
        float mean = stats_s[fl * 2], rstd = stats_s[fl * 2 + 1];
        float4 rw, cc, x;
        rw.x = rstd * w4.x; rw.y = rstd * w4.y; rw.z = rstd * w4.z; rw.w = rstd * w4.w;
        cc.x = c4.x - mean * rw.x; cc.y = c4.y - mean * rw.y;
        cc.z = c4.z - mean * rw.z; cc.w = c4.w - mean * rw.w;
        x.x = v.x * rw.x + cc.x; x.y = v.y * rw.y + cc.y;
        x.z = v.z * rw.z + cc.z; x.w = v.w * rw.w + cc.w;
        float4 aA = *(const float4*)&attn_s[fl * 8];
        float4 aB = *(const float4*)&attn_s[fl * 8 + 4];
        float a[8] = {aA.x + kEPS, aA.y + kEPS, aA.z + kEPS, aA.w + kEPS,
                      aB.x + kEPS, aB.y + kEPS, aB.z + kEPS, aB.w + kEPS};
#pragma unroll
        for (int s = 0; s < 8; s++) {
            acc[s].x += a[s] * x.x; acc[s].y += a[s] * x.y;
            acc[s].z += a[s] * x.z; acc[s].w += a[s] * x.w;
        }
    }
    __syncthreads();     // attn_s / qk_s reads done; reuse qk_s for reduction
    if (half == 0) {
#pragma unroll
        for (int s = 0; s < 8; s++) *(float4*)&qk_s[s * D_ + d4] = acc[s];
    }
    __syncthreads();
    if (half == 1) {
        size_t base = ((size_t)(b * NCHUNK + chunk)) * S_ * D_;
#pragma unroll
        for (int s = 0; s < 8; s++) {
            float4 o = *(const float4*)&qk_s[s * D_ + d4];
            o.x += acc[s].x; o.y += acc[s].y; o.z += acc[s].z; o.w += acc[s].w;
            *(float4*)(&g_Upart[base + s * D_ + d4]) = o;
        }
    }
}

// deterministic reduction of partials + rowsum normalization
__global__ void reduce_updates_kernel() {
    int bs = blockIdx.x;           // b*8+s
    int b = bs >> 3, s = bs & 7;
    int d = threadIdx.x;           // 512 threads
    float rs = 0.f;
#pragma unroll
    for (int c = 0; c < NCHUNK; c++) rs += g_rspart[(b * NCHUNK + c) * 8 + s];
    float acc = 0.f;
    for (int c = 0; c < NCHUNK; c++)
        acc += g_Upart[(((size_t)(b * NCHUNK + c)) * S_ + s) * D_ + d];
    g_updates[(size_t)bs * D_ + d] = acc / rs;
}

// -------------------- host orchestration -----------------------------------
extern "C" void kernel_launch(void* const* d_in, const int* in_sizes, int n_in,
                              void* d_out, int out_size) {
    const float* slots_in = (const float*)d_in[0];
    const float* features = (const float*)d_in[1];
    const float* w_k      = (const float*)d_in[2];
    const float* w_v      = (const float*)d_in[3];
    const float* w_q      = (const float*)d_in[4];
    const float* ln_feat_w = (const float*)d_in[5];
    const float* ln_feat_b = (const float*)d_in[6];
    const float* ln_slot_w = (const float*)d_in[7];
    const float* ln_slot_b = (const float*)d_in[8];
    const float* gru_w_ih = (const float*)d_in[9];
    const float* gru_w_hh = (const float*)d_in[10];
    const float* gru_b_ih = (const float*)d_in[11];
    const float* gru_b_hh = (const float*)d_in[12];
    const float* ln_mlp_w = (const float*)d_in[13];
    const float* ln_mlp_b = (const float*)d_in[14];
    const float* mlp_w1   = (const float*)d_in[15];
    const float* mlp_b1   = (const float*)d_in[16];
    const float* mlp_w2   = (const float*)d_in[17];
    const float* mlp_b2   = (const float*)d_in[18];

    float* out = (float*)d_out;
    float* out_slots = out;                      // [32,8,512]
    float* out_attn  = out + B_ * S_ * D_;       // [32,8,4096]

    float *p_Wqkhh, *p_bias2048, *p_Wvih, *p_sn, *p_qkgh, *p_gi,
          *p_updates, *p_mlpin, *p_hbuf, *p_split;
    cudaGetSymbolAddress((void**)&p_Wqkhh, g_Wqkhh);
    cudaGetSymbolAddress((void**)&p_bias2048, g_bias2048);
    cudaGetSymbolAddress((void**)&p_Wvih, g_Wvih);
    cudaGetSymbolAddress((void**)&p_sn, g_sn);
    cudaGetSymbolAddress((void**)&p_qkgh, g_qkgh);
    cudaGetSymbolAddress((void**)&p_gi, g_gi);
    cudaGetSymbolAddress((void**)&p_updates, g_updates);
    cudaGetSymbolAddress((void**)&p_mlpin, g_mlpin);
    cudaGetSymbolAddress((void**)&p_hbuf, g_hbuf);
    cudaGetSymbolAddress((void**)&p_split, g_split);

    const int NS = B_ * S_;          // 256 slot rows

    // -------- precomputes --------
    feat_stats_kernel<<<(B_ * F_) / 8, 256>>>(features);
    // Wqk tmp = w_q @ w_k^T  (NT, split-2) -> g_gi (reused as tmp)
    gemm64_kernel<true><<<dim3(8, 8, 2), 128>>>(w_q, w_k, p_split, D_, D_, D_, D_);
    splitk_reduce<false><<<(512 * 512 + 255) / 256, 256>>>(nullptr, p_gi,
        512 * 512, 512, 512, 2, 512 * 512);
    // W_vih = w_v @ w_ih^T  (NT, split-2)
    gemm64_kernel<true><<<dim3(24, 8, 2), 128>>>(w_v, gru_w_ih, p_split, D_, 3 * D_, D_, 3 * D_);
    splitk_reduce<false><<<(512 * 1536 + 255) / 256, 256>>>(nullptr, p_Wvih,
        512 * 1536, 1536, 1536, 2, 512 * 1536);
    // pack Wqkhh + bias
    build_whh_kernel<<<(512 * 2048) / 256, 256>>>(gru_w_hh, gru_b_hh, p_gi);

    for (int it = 0; it < NITERS_; it++) {
        bool last = (it == NITERS_ - 1);

        if (it == 0)
            ln_rows_kernel<<<NS, 128>>>(slots_in, p_sn, ln_slot_w, ln_slot_b);

        // [qk | gh] = s_n @ Wqkhh + [0 | b_hh]   (NN, N=2048, split-8)
        gemm64_kernel<false><<<dim3(32, 4, 8), 128>>>(p_sn, p_Wqkhh, p_split,
                                                      NS, 2048, D_, 2048);
        splitk_reduce<false><<<(NS * 2048 + 255) / 256, 256>>>(p_bias2048, p_qkgh,
            NS * 2048, 2048, 2048, 8, NS * 2048);

        // fused attention pass over features
        iter_pass_kernel<<<dim3(NCHUNK, B_), 256>>>(features, ln_feat_w, ln_feat_b,
                                                    last ? out_attn : nullptr);
        reduce_updates_kernel<<<NS, D_>>>();

        // gi = updates @ W_vih + b_ih   (NN, N=1536, split-8)
        gemm64_kernel<false><<<dim3(24, 4, 8), 128>>>(p_updates, p_Wvih, p_split,
                                                      NS, 3 * D_, D_, 3 * D_);
        splitk_reduce<false><<<(NS * 1536 + 255) / 256, 256>>>(gru_b_ih, p_gi,
            NS * 1536, 1536, 1536, 8, NS * 1536);

        // GRU combine + LN(mlp) fused
        gru_ln_kernel<<<NS, D_>>>(ln_mlp_w, ln_mlp_b);

        // mlp1 = relu(mlpin @ w1 + b1)   (NN, N=2048, split-8)
        gemm64_kernel<false><<<dim3(32, 4, 8), 128>>>(p_mlpin, mlp_w1, p_split,
                                                      NS, H_, D_, H_);
        splitk_reduce<true><<<(NS * 2048 + 255) / 256, 256>>>(mlp_b1, p_hbuf,
            NS * 2048, 2048, 2048, 8, NS * 2048);

        // mlp2 partials (NN, N=512, K=2048, split-16)
        gemm64_kernel<false><<<dim3(8, 4, 16), 128>>>(p_hbuf, mlp_w2, p_split,
                                                      NS, D_, H_, D_);
        // reduce + bias + residual + LN(slot) -> sn (and out_slots if last)
        mlp2_reduce_ln<<<NS, D_>>>(mlp_b2, ln_slot_w, ln_slot_b,
                                   last ? out_slots : nullptr);
    }
}